// round 15
// baseline (speedup 1.0000x reference)
#include <cuda_runtime.h>
#include <math.h>

#define SB 200
#define TB 200
#define BB 256
#define HH 512
#define VV 512
#define NB 128    // persistent blocks, all co-resident (1 per SM)
#define NT 256

// ---------------- device scratch ----------------
__device__ float g_eo[SB * BB * HH];      // encoder outputs (S,B,H)
__device__ float g_qpre[TB * BB * HH];    // de @ mlpW[:, :512]^T
__device__ float g_h[2][BB * HH];         // hidden ping-pong
__device__ float g_xv[BB * HH];           // decoder GRU input x
__device__ float g_ctx[BB * HH];          // attention context
__device__ float g_ah[BB * HH];           // relu(h @ att_W^T + att_b)
__device__ float g_logits[BB * VV];       // logits (bias included)
__device__ float g_loss_tb[TB * BB];

// ---------------- grid barrier (proven atomic version) ---------------------
__device__ unsigned g_cnt = 0;
__device__ volatile unsigned g_gen = 0;

__device__ __forceinline__ void gsync() {
    __syncthreads();
    if (threadIdx.x == 0) {
        __threadfence();
        unsigned gen = g_gen;
        if (atomicAdd(&g_cnt, 1u) == NB - 1) {
            g_cnt = 0;
            __threadfence();
            g_gen = gen + 1;
        } else {
            while (g_gen == gen) { }
        }
        __threadfence();
    }
    __syncthreads();
}

// ---------------- additive bank-shift swizzles ------------------------------
// Store row k shifts columns by +4*((k>>3)&3) words (16B arrays) or
// +2*((k>>3)&3) (8B arrays). Pitches padded so no wrap. In unrolled loops the
// load-side shift is a compile-time immediate (no extra registers).
#define SA(k) ((((k) >> 3) & 3) * 4)
#define SBq(k) ((((k) >> 3) & 3) * 2)

// padded pitches (words)
#define PA  144   // GRU A slab (was 132)
#define PWP 48    // Wp (was 36)
#define PWQ 24    // Wq (was 18)
#define PGA 80    // gemm A slab (was 68)
#define PGB2 80   // gemm Bs JW=2 (was 68)
#define PGB1 40   // gemm Bs JW=1 (was 34)

// ---------------- shared memory layout (dynamic) ----------------
// [0      : 36864)  As2[2][32][144]  dup'd A, double-buffered (GRU)
// [36864  : 49152)  Wps[2][32][48]   streamed Wih r/z
// [49152  : 55296)  Wqs[2][32][24]   streamed Wih n
// [55296  : 55552)  tokS[64]
// [55552  : 153856) Wpc[16][32][48]  PERSISTENT cached Whh r/z
// [153856 : 203008) Wqc[16][32][24]  PERSISTENT cached Whh n
// gemm_core uses [0:41KB); attn 18.5KB; out 3KB — all below 55552.
#define OFF_WPS 36864
#define OFF_WQS 49152
#define OFF_TOK 55296
#define OFF_WPC 55552
#define OFF_WQC 153856
#define SMEM_BYTES 203008

extern __shared__ char raw[];

#define FMA2(acc, a, b) \
    asm("fma.rn.f32x2 %0, %1, %2, %0;" : "+l"(acc) : "l"(a), "l"(b))

__device__ __forceinline__ float2 u2f2(unsigned long long v) {
    float2 r;
    asm("mov.b64 {%0, %1}, %2;" : "=f"(r.x), "=f"(r.y) : "l"(v));
    return r;
}

// ---------------- load this block's Whh tile into the persistent cache -----
__device__ void load_whh_cache(const float* __restrict__ Whh) {
    const int tid = threadIdx.x;
    const int lk = tid & 31, lr = tid >> 5;
    const int jB = (blockIdx.x >> 2) * 16;
    float* Wpc = (float*)(raw + OFF_WPC) + lk * PWP + SA(lk);
    float* Wqc = (float*)(raw + OFF_WQC) + lk * PWQ + SBq(lk);
#pragma unroll 4
    for (int kc16 = 0; kc16 < 16; kc16++) {
#pragma unroll
        for (int i = 0; i < 6; i++) {
            int r = lr + 8 * i, g = r >> 4, j = r & 15;
            float w = Whh[(size_t)(g * HH + jB + j) * HH + (kc16 << 5) + lk];
            if (g < 2) Wpc[kc16 * (32 * PWP) + (j >> 1) * 4 + 2 * g + (j & 1)] = w;
            else       Wqc[kc16 * (32 * PWQ) + j] = w;
        }
    }
    __syncthreads();
}

// ---------------- GRU step: 128 tiles of 64b x 16j x 3 gates ---------------
// FMA chains bitwise identical to rounds 8/11. Smem stores bank-shifted.
template <bool ENC>
__device__ void gru_step(
    int s, const int* __restrict__ iseq, const float* __restrict__ eemb,
    const float* __restrict__ Xv,
    const float* __restrict__ Hin, float* __restrict__ Hout,
    float* __restrict__ eout,
    const float* __restrict__ Wih,
    const float* __restrict__ bih, const float* __restrict__ bhh,
    const int* __restrict__ ilen) {

    float* As2 = (float*)raw;                       // [2][32][PA]
    float* Wps = (float*)(raw + OFF_WPS);           // [2][32][PWP]
    float* Wqs = (float*)(raw + OFF_WQS);           // [2][32][PWQ]
    int* tokS  = (int*)(raw + OFF_TOK);

    const int tid = threadIdx.x;
    const int lk = tid & 31, lr = tid >> 5;       // loader coords
    const int tx = tid & 7;                       // j-pair
    const int cA = (tid >> 3) * 4;                // a-load column base
    const int bB = (blockIdx.x & 3) * 64;
    const int jB = (blockIdx.x >> 2) * 16;

    // store-side base pointers with per-thread shift folded in
    float* stA = As2 + lk * PA + SA(lk);
    float* stP = Wps + lk * PWP + SA(lk);
    float* stQ = Wqs + lk * PWQ + SBq(lk);

    if (ENC) {
        if (tid < 64) tokS[tid] = iseq[s * BB + bB + tid];
    }
    __syncthreads();

    unsigned long long ar2[2]  = {0ull, 0ull};
    unsigned long long az2[2]  = {0ull, 0ull};
    unsigned long long ani2[2] = {0ull, 0ull};
    unsigned long long anh2[2] = {0ull, 0ull};

    float av[8], wv[6];

    auto ldA = [&](int ph, int kc) {
        if (ph == 0) {
            if (ENC) {
#pragma unroll
                for (int i = 0; i < 8; i++)
                    av[i] = eemb[(size_t)tokS[lr + 8 * i] * HH + kc + lk];
            } else {
#pragma unroll
                for (int i = 0; i < 8; i++)
                    av[i] = Xv[(size_t)(bB + lr + 8 * i) * HH + kc + lk];
            }
        } else {
#pragma unroll
            for (int i = 0; i < 8; i++)
                av[i] = Hin[(size_t)(bB + lr + 8 * i) * HH + kc + lk];
        }
    };
    auto ldW = [&](int kc) {   // Wih only (Whh is cached)
#pragma unroll
        for (int i = 0; i < 6; i++) {
            int r = lr + 8 * i;                   // 0..47
            int g = r >> 4, j = r & 15;
            wv[i] = Wih[(size_t)(g * HH + jB + j) * HH + kc + lk];
        }
    };
    auto stbA = [&](int buf) {
#pragma unroll
        for (int i = 0; i < 8; i++)
            *(float2*)&stA[buf * (32 * PA) + 2 * (lr + 8 * i)] =
                make_float2(av[i], av[i]);
    };
    auto stbW = [&](int buf) {
#pragma unroll
        for (int i = 0; i < 6; i++) {
            int r = lr + 8 * i;
            int g = r >> 4, j = r & 15;
            if (g < 2)
                stP[buf * (32 * PWP) + (j >> 1) * 4 + 2 * g + (j & 1)] = wv[i];
            else
                stQ[buf * (32 * PWQ) + j] = wv[i];
        }
    };

#define GRU_INNER(AN, WP, WQ, ABASE)                                           \
    _Pragma("unroll")                                                          \
    for (int kk = 0; kk < 32; kk++) {                                          \
        ulonglong2 a2 =                                                        \
            *(const ulonglong2*)((ABASE) + kk * PA + SA(kk) + cA);             \
        ulonglong2 w01 =                                                       \
            *(const ulonglong2*)((WP) + kk * PWP + SA(kk) + tx * 4);           \
        unsigned long long w2 = *(const unsigned long long*)                   \
            ((WQ) + kk * PWQ + SBq(kk) + tx * 2);                              \
        FMA2(ar2[0], a2.x, w01.x); FMA2(ar2[1], a2.y, w01.x);                  \
        FMA2(az2[0], a2.x, w01.y); FMA2(az2[1], a2.y, w01.y);                  \
        FMA2(AN[0],  a2.x, w2);    FMA2(AN[1],  a2.y, w2);                     \
    }

    // prologue: chunk 0 (Wih phase)
    ldA(0, 0); ldW(0); stbA(0); stbW(0);
    __syncthreads();

    for (int c = 0; c < 32; c++) {
        const int buf = c & 1;
        if (c < 31) {
            const int nc = c + 1;
            ldA(nc >> 4, (nc & 15) << 5);
            if (nc < 16) ldW(nc << 5);
        }
        const float* ab = As2 + buf * (32 * PA);
        const float* wp = (c < 16) ? (Wps + buf * (32 * PWP))
                                   : (const float*)(raw + OFF_WPC) + (c - 16) * (32 * PWP);
        const float* wq = (c < 16) ? (Wqs + buf * (32 * PWQ))
                                   : (const float*)(raw + OFF_WQC) + (c - 16) * (32 * PWQ);
        if (c < 16) { GRU_INNER(ani2, wp, wq, ab) } else { GRU_INNER(anh2, wp, wq, ab) }
        if (c < 31) {
            stbA(buf ^ 1);
            if (c + 1 < 16) stbW(buf ^ 1);
        }
        __syncthreads();
    }
#undef GRU_INNER

    float2 arf[2]  = {u2f2(ar2[0]), u2f2(ar2[1])};
    float2 azf[2]  = {u2f2(az2[0]), u2f2(az2[1])};
    float2 anif[2] = {u2f2(ani2[0]), u2f2(ani2[1])};
    float2 anhf[2] = {u2f2(anh2[0]), u2f2(anh2[1])};

    const int ty = tid >> 3;
#pragma unroll
    for (int r = 0; r < 2; r++) {
        int b = bB + ty * 2 + r;
#pragma unroll
        for (int l = 0; l < 2; l++) {
            int j = jB + tx * 2 + l;
            float ar  = l ? arf[r].y  : arf[r].x;
            float az  = l ? azf[r].y  : azf[r].x;
            float ani = l ? anif[r].y : anif[r].x;
            float anh = l ? anhf[r].y : anhf[r].x;
            float rr = 1.f / (1.f + expf(-(ar + bih[j] + bhh[j])));
            float zz = 1.f / (1.f + expf(-(az + bih[HH + j] + bhh[HH + j])));
            float nn = tanhf(ani + bih[2 * HH + j] + rr * (anh + bhh[2 * HH + j]));
            float hp = Hin[b * HH + j];
            float hnew = (1.f - zz) * nn + zz * hp;
            if (ENC) {
                bool m = s < ilen[b];
                float ho = m ? hnew : hp;
                Hout[b * HH + j] = ho;
                eout[b * HH + j] = m ? ho : 0.f;
            } else {
                Hout[b * HH + j] = hnew;
            }
        }
    }
}

// ---------------- 32b x (32*JW)n GEMM core, K=512, double-buffered ----------
// (round-11 version + additive bank shifts)
template <int JW>
__device__ __forceinline__ void gemm_core(
    const float* const* pA, const float* const* pB,
    unsigned long long (&acc)[2][JW]) {
    float* As2 = (float*)raw;                         // [2][32][PGA]
    const int BW = (JW == 2) ? PGB2 : PGB1;
    float* Bs = (float*)(raw + 2 * 32 * PGA * 4);     // [2][32][BW]
    const int tid = threadIdx.x;
    const int lk = tid & 31, lr = tid >> 5;
    const int tx = tid & 15, ty = tid >> 4;
    float* stA = As2 + lk * PGA + SA(lk);
    float* stB = Bs + lk * BW + (JW == 2 ? SA(lk) : SBq(lk));
    float av[4], bv[4 * JW];
    auto ld = [&](int kc) {
#pragma unroll
        for (int i = 0; i < 4; i++) av[i] = pA[i][kc + lk];
#pragma unroll
        for (int i = 0; i < 4 * JW; i++) bv[i] = pB[i][kc + lk];
    };
    auto st = [&](int buf) {
#pragma unroll
        for (int i = 0; i < 4; i++)
            *(float2*)&stA[buf * (32 * PGA) + 2 * (lr + 8 * i)] =
                make_float2(av[i], av[i]);
#pragma unroll
        for (int i = 0; i < 4 * JW; i++)
            stB[buf * (32 * BW) + lr + 8 * i] = bv[i];
    };
    ld(0); st(0);
    __syncthreads();
    for (int c = 0; c < 16; c++) {
        const int buf = c & 1;
        if (c < 15) ld((c + 1) * 32);
        const float* ab = As2 + buf * (32 * PGA);
        const float* bb = Bs + buf * (32 * BW);
#pragma unroll
        for (int kk = 0; kk < 32; kk++) {
            ulonglong2 a2 =
                *(const ulonglong2*)(ab + kk * PGA + SA(kk) + ty * 4);
            if (JW == 2) {
                ulonglong2 wq =
                    *(const ulonglong2*)(bb + kk * BW + SA(kk) + tx * 4);
                FMA2(acc[0][0], a2.x, wq.x);
                FMA2(acc[1][0], a2.y, wq.x);
                FMA2(acc[0][JW - 1], a2.x, wq.y);
                FMA2(acc[1][JW - 1], a2.y, wq.y);
            } else {
                unsigned long long wq = *(const unsigned long long*)
                    (bb + kk * BW + SBq(kk) + tx * 2);
                FMA2(acc[0][0], a2.x, wq);
                FMA2(acc[1][0], a2.y, wq);
            }
        }
        if (c < 15) st(buf ^ 1);
        __syncthreads();
    }
}

// ---------------- qpre: de @ mlpW[:, :512]^T ----------------
__device__ void qpre_phase(const int* __restrict__ tseq,
                           const float* __restrict__ demb,
                           const float* __restrict__ mlpW) {
    const int tid = threadIdx.x;
    const int lr = tid >> 5;
    const int tx = tid & 15, ty = tid >> 4;
    for (int tile = blockIdx.x; tile < 12800; tile += NB) {
        int rowt = tile >> 3, nt = tile & 7;
        int r0 = rowt * 32, n0 = nt * 64;
        const float* pA[4];
        const float* pB[8];
#pragma unroll
        for (int i = 0; i < 4; i++) {
            int r = r0 + lr + 8 * i;
            int t = r >> 8, b = r & 255;
            int tok = (t == 0) ? 1 : tseq[(t - 1) * BB + b];
            pA[i] = demb + (size_t)tok * HH;
        }
#pragma unroll
        for (int i = 0; i < 8; i++)
            pB[i] = mlpW + (size_t)(n0 + lr + 8 * i) * 1024;
        unsigned long long acc[2][2] = {{0ull, 0ull}, {0ull, 0ull}};
        gemm_core<2>(pA, pB, acc);
#pragma unroll
        for (int r = 0; r < 2; r++) {
            int row = r0 + ty * 2 + r;
#pragma unroll
            for (int p = 0; p < 2; p++) {
                float2 v = u2f2(acc[r][p]);
                *(float2*)&g_qpre[(size_t)row * HH + n0 + tx * 4 + 2 * p] = v;
            }
        }
        __syncthreads();
    }
}

// ---------------- mlp ctx half: acc starts at qpre, k=512..1023 -------------
__device__ void mlp_phase(int t, const float* __restrict__ mlpW,
                          const float* __restrict__ mlpb) {
    const int tid = threadIdx.x;
    const int lr = tid >> 5;
    const int tx = tid & 15, ty = tid >> 4;
    const int bB = (blockIdx.x & 7) * 32, n0 = (blockIdx.x >> 3) * 32;
    const float* pA[4];
    const float* pB[4];
#pragma unroll
    for (int i = 0; i < 4; i++) {
        pA[i] = g_ctx + (size_t)(bB + lr + 8 * i) * HH;
        pB[i] = mlpW + (size_t)(n0 + lr + 8 * i) * 1024 + 512;
    }
    unsigned long long acc[2][1];
#pragma unroll
    for (int r = 0; r < 2; r++)
        acc[r][0] = *(const unsigned long long*)
            &g_qpre[(size_t)(t * BB + bB + ty * 2 + r) * HH + n0 + tx * 2];
    gemm_core<1>(pA, pB, acc);
#pragma unroll
    for (int r = 0; r < 2; r++) {
        int b = bB + ty * 2 + r;
        float2 v = u2f2(acc[r][0]);
        int j0 = n0 + tx * 2;
        g_xv[b * HH + j0]     = tanhf(v.x + mlpb[j0]);
        g_xv[b * HH + j0 + 1] = tanhf(v.y + mlpb[j0 + 1]);
    }
}

// ---------------- fused logits(t) + ah(t+1): N=1024, full-K sequential ------
__device__ void logah_phase(const float* __restrict__ h,
                            const float* __restrict__ outW,
                            const float* __restrict__ attW,
                            const float* __restrict__ outb,
                            const float* __restrict__ attb) {
    const int tid = threadIdx.x;
    const int lr = tid >> 5;
    const int tx = tid & 15, ty = tid >> 4;
    const int bB = (blockIdx.x & 7) * 32, n0 = (blockIdx.x >> 3) * 64;
    const float* pA[4];
    const float* pB[8];
#pragma unroll
    for (int i = 0; i < 4; i++)
        pA[i] = h + (size_t)(bB + lr + 8 * i) * HH;
#pragma unroll
    for (int i = 0; i < 8; i++) {
        int n = n0 + lr + 8 * i;
        pB[i] = (n < 512) ? outW + (size_t)n * HH : attW + (size_t)(n - 512) * HH;
    }
    unsigned long long acc[2][2] = {{0ull, 0ull}, {0ull, 0ull}};
    gemm_core<2>(pA, pB, acc);
#pragma unroll
    for (int r = 0; r < 2; r++) {
        int b = bB + ty * 2 + r;
#pragma unroll
        for (int p = 0; p < 2; p++) {
            float2 v = u2f2(acc[r][p]);
#pragma unroll
            for (int l = 0; l < 2; l++) {
                int n = n0 + tx * 4 + 2 * p + l;
                float val = l ? v.y : v.x;
                if (n < 512)
                    g_logits[b * VV + n] = val + outb[n];
                else
                    g_ah[b * HH + n - 512] = fmaxf(val + attb[n - 512], 0.f);
            }
        }
    }
}

// ---------------- attention (numerics unchanged since round 2) --------------
__device__ void attn_one(int b) {
    float* ah   = (float*)raw;
    float* wm   = ah + 512;
    float* wsum = wm + 8;
    float* wctx = wsum + 8;

    const int tid = threadIdx.x, warp = tid >> 5, lane = tid & 31;
    ah[tid]       = g_ah[b * HH + tid];
    ah[tid + 256] = g_ah[b * HH + tid + 256];
    __syncthreads();

    float ahr[16];
#pragma unroll
    for (int i = 0; i < 16; i++) ahr[i] = ah[lane + 32 * i];

    float m = -1e30f, s = 0.f;
    float ctx[16];
#pragma unroll
    for (int i = 0; i < 16; i++) ctx[i] = 0.f;

    for (int sI = warp; sI < SB; sI += 8) {
        const float* eo = g_eo + ((size_t)sI * BB + b) * HH;
        float ev[16], d = 0.f;
#pragma unroll
        for (int i = 0; i < 16; i++) { ev[i] = eo[lane + 32 * i]; d += ev[i] * ahr[i]; }
#pragma unroll
        for (int o = 16; o > 0; o >>= 1) d += __shfl_xor_sync(0xffffffffu, d, o);
        float mn = fmaxf(m, d);
        float sc = expf(m - mn);
        float p  = expf(d - mn);
        s = s * sc + p;
#pragma unroll
        for (int i = 0; i < 16; i++) ctx[i] = ctx[i] * sc + p * ev[i];
        m = mn;
    }
    if (lane == 0) { wm[warp] = m; wsum[warp] = s; }
#pragma unroll
    for (int i = 0; i < 16; i++) wctx[warp * 512 + lane + 32 * i] = ctx[i];
    __syncthreads();

    float M = -1e30f;
#pragma unroll
    for (int w = 0; w < 8; w++) M = fmaxf(M, wm[w]);
    float S = 0.f, esc[8];
#pragma unroll
    for (int w = 0; w < 8; w++) { esc[w] = expf(wm[w] - M); S += wsum[w] * esc[w]; }
    float inv = 1.f / S;
#pragma unroll
    for (int hh = 0; hh < 2; hh++) {
        int h = tid + hh * 256;
        float acc = 0.f;
#pragma unroll
        for (int w = 0; w < 8; w++) acc += esc[w] * wctx[w * 512 + h];
        g_ctx[b * HH + h] = acc * inv;
    }
    __syncthreads();
}

// ---------------- output softmax/argmax/loss (numerics unchanged) -----------
__device__ void out_one(int t, int b, const int* __restrict__ tseq,
                        float* __restrict__ dout) {
    float* sv = (float*)raw;
    int*   si = (int*)(raw + 1024);
    const int tid = threadIdx.x;
    const float* lrow = g_logits + b * VV;
    float v0 = lrow[tid], v1 = lrow[tid + 256];
    float mv; int mi;
    if (v0 >= v1) { mv = v0; mi = tid; } else { mv = v1; mi = tid + 256; }
    sv[tid] = mv; si[tid] = mi;
    __syncthreads();
    for (int o = 128; o > 0; o >>= 1) {
        if (tid < o) {
            float ov = sv[tid + o]; int oi = si[tid + o];
            if (ov > sv[tid] || (ov == sv[tid] && oi < si[tid])) { sv[tid] = ov; si[tid] = oi; }
        }
        __syncthreads();
    }
    float bmax = sv[0];
    int pred = si[0];
    __syncthreads();
    sv[tid] = expf(v0 - bmax) + expf(v1 - bmax);
    __syncthreads();
    for (int o = 128; o > 0; o >>= 1) {
        if (tid < o) sv[tid] += sv[tid + o];
        __syncthreads();
    }
    if (tid == 0) {
        int tgt = tseq[t * BB + b];
        float p = expf(lrow[tgt] - bmax) / sv[0];
        p = fmaxf(p, 1e-10f);
        g_loss_tb[t * BB + b] = -logf(p);
        dout[t * BB + b] = (float)pred;
    }
    __syncthreads();
}

// ---------------- persistent mega-kernel ----------------
__global__ void __launch_bounds__(NT) k_mega(
    const int* __restrict__ iseq, const int* __restrict__ ilen,
    const int* __restrict__ tseq,
    const float* __restrict__ eemb,
    const float* __restrict__ eWih, const float* __restrict__ eWhh,
    const float* __restrict__ ebih, const float* __restrict__ ebhh,
    const float* __restrict__ attW, const float* __restrict__ attb,
    const float* __restrict__ demb,
    const float* __restrict__ dWih, const float* __restrict__ dWhh,
    const float* __restrict__ dbih, const float* __restrict__ dbhh,
    const float* __restrict__ mlpW, const float* __restrict__ mlpb,
    const float* __restrict__ outW, const float* __restrict__ outb,
    float* __restrict__ dout) {

    const int bid = blockIdx.x, tid = threadIdx.x;

    for (int i = bid * NT + tid; i < BB * HH; i += NB * NT) g_h[0][i] = 0.f;
    gsync();

    qpre_phase(tseq, demb, mlpW);
    gsync();

    // encoder: cache eWhh tile once, then 200 steps
    load_whh_cache(eWhh);
    for (int s = 0; s < SB; s++) {
        int pin = s & 1;
        gru_step<true>(s, iseq, eemb, nullptr, g_h[pin], g_h[pin ^ 1],
                       g_eo + (size_t)s * BB * HH,
                       eWih, ebih, ebhh, ilen);
        gsync();
    }

    // ah for t=0 (logits half junk, never read)
    logah_phase(g_h[0], outW, attW, outb, attb);
    gsync();

    // decoder: cache dWhh tile once, then 200 steps, 4 barriers each
    load_whh_cache(dWhh);
    for (int t = 0; t < TB; t++) {
        int pin = t & 1;
        if (t > 0) {
            out_one(t - 1, bid * 2 + 0, tseq, dout);
            out_one(t - 1, bid * 2 + 1, tseq, dout);
        }
        attn_one(bid * 2 + 0);
        attn_one(bid * 2 + 1);
        gsync();
        mlp_phase(t, mlpW, mlpb);
        gsync();
        gru_step<false>(0, nullptr, nullptr, g_xv, g_h[pin], g_h[pin ^ 1],
                        nullptr, dWih, dbih, dbhh, nullptr);
        gsync();
        logah_phase(g_h[pin ^ 1], outW, attW, outb, attb);
        gsync();
    }
    out_one(TB - 1, bid * 2 + 0, tseq, dout);
    out_one(TB - 1, bid * 2 + 1, tseq, dout);
    gsync();

    if (bid != 0) return;
    {
        float* sf = (float*)raw;
        int*   sc = (int*)(raw + 1024);
        int*   sa = (int*)(raw + 2048);
        float ls = 0.f; int corr = 0;
        for (int i = tid; i < TB * BB; i += NT) {
            ls += g_loss_tb[i];
            corr += (dout[i] == (float)tseq[i]) ? 1 : 0;
        }
        int allc = 1;
        for (int t = 0; t < TB; t++)
            if (dout[t * BB + tid] != (float)tseq[t * BB + tid]) { allc = 0; break; }
        sf[tid] = ls; sc[tid] = corr; sa[tid] = allc;
        __syncthreads();
        for (int o = 128; o > 0; o >>= 1) {
            if (tid < o) { sf[tid] += sf[tid + o]; sc[tid] += sc[tid + o]; sa[tid] += sa[tid + o]; }
            __syncthreads();
        }
        if (tid == 0) {
            dout[TB * BB]     = sf[0] / (float)(TB * BB);
            dout[TB * BB + 1] = (float)sa[0] / (float)BB;
            dout[TB * BB + 2] = (float)sc[0] / (float)(TB * BB);
        }
    }
}

// ---------------- host ----------------
extern "C" void kernel_launch(void* const* d_in, const int* in_sizes, int n_in,
                              void* d_out, int out_size) {
    (void)in_sizes; (void)n_in; (void)out_size;
    cudaFuncSetAttribute(k_mega, cudaFuncAttributeMaxDynamicSharedMemorySize,
                         SMEM_BYTES);
    k_mega<<<NB, NT, SMEM_BYTES>>>(
        (const int*)d_in[0], (const int*)d_in[1], (const int*)d_in[2],
        (const float*)d_in[3], (const float*)d_in[4], (const float*)d_in[5],
        (const float*)d_in[6], (const float*)d_in[7], (const float*)d_in[8],
        (const float*)d_in[9], (const float*)d_in[10], (const float*)d_in[11],
        (const float*)d_in[12], (const float*)d_in[13], (const float*)d_in[14],
        (const float*)d_in[15], (const float*)d_in[16], (const float*)d_in[17],
        (const float*)d_in[18], (float*)d_out);
}

// round 16
// speedup vs baseline: 1.0389x; 1.0389x over previous
#include <cuda_runtime.h>
#include <math.h>

#define SB 200
#define TB 200
#define BB 256
#define HH 512
#define VV 512
#define NB 128    // persistent blocks, all co-resident (1 per SM)
#define NT 256

// ---------------- device scratch ----------------
__device__ float g_eo[SB * BB * HH];      // encoder outputs (S,B,H)
__device__ float g_qpre[TB * BB * HH];    // de @ mlpW[:, :512]^T
__device__ float g_h[2][BB * HH];         // hidden ping-pong
__device__ float g_xv[BB * HH];           // decoder GRU input x
__device__ float g_ctx[BB * HH];          // attention context
__device__ float g_ah[BB * HH];           // relu(h @ att_W^T + att_b)
__device__ float g_logits[BB * VV];       // logits (bias included)
__device__ float g_loss_tb[TB * BB];

// ---------------- hierarchical grid barrier ---------------------------------
// Level 1: 8 padded group counters (16 arrivals each) on separate L2 lines.
// Level 2: master counter (8 arrivals). All waiters spin on g_gen.
// Same release/acquire fences + monotonic generation as the flat version.
__device__ unsigned g_cnt1[8 * 32];   // stride 32 words -> 128B apart
__device__ unsigned g_cnt2 = 0;
__device__ volatile unsigned g_gen = 0;

__device__ __forceinline__ void gsync() {
    __syncthreads();
    if (threadIdx.x == 0) {
        __threadfence();                         // release this block's writes
        unsigned gen = g_gen;
        if (atomicAdd(&g_cnt1[(blockIdx.x & 7) * 32], 1u) == 15) {
            g_cnt1[(blockIdx.x & 7) * 32] = 0;   // group complete
            if (atomicAdd(&g_cnt2, 1u) == 7) {
                g_cnt2 = 0;
                __threadfence();
                g_gen = gen + 1;                 // release all
            } else {
                while (g_gen == gen) { }
            }
        } else {
            while (g_gen == gen) { }
        }
        __threadfence();                         // acquire others' writes
    }
    __syncthreads();
}

// ---------------- shared memory layout (dynamic) ----------------
// [0      : 33792)  As2[2][32][132]  dup'd A, double-buffered (GRU)
// [33792  : 43008)  Wps[2][32][36]   streamed Wih r/z
// [43008  : 47616)  Wqs[2][32][18]   streamed Wih n
// [47616  : 47872)  tokS[64]
// [48128  : 121856) Wpc[16][32][36]  PERSISTENT cached Whh r/z
// [121856 : 158720) Wqc[16][32][18]  PERSISTENT cached Whh n
// Other phases (gemm_core <35KB, attn 18.5KB, out 3KB) only touch < 48128.
#define OFF_WPS 33792
#define OFF_WQS 43008
#define OFF_TOK 47616
#define OFF_WPC 48128
#define OFF_WQC 121856
#define SMEM_BYTES 158720

extern __shared__ char raw[];

#define FMA2(acc, a, b) \
    asm("fma.rn.f32x2 %0, %1, %2, %0;" : "+l"(acc) : "l"(a), "l"(b))

__device__ __forceinline__ float2 u2f2(unsigned long long v) {
    float2 r;
    asm("mov.b64 {%0, %1}, %2;" : "=f"(r.x), "=f"(r.y) : "l"(v));
    return r;
}

// ---------------- load this block's Whh tile into the persistent cache -----
__device__ void load_whh_cache(const float* __restrict__ Whh) {
    float (*Wpc)[32][36] = (float (*)[32][36])(raw + OFF_WPC);
    float (*Wqc)[32][18] = (float (*)[32][18])(raw + OFF_WQC);
    const int tid = threadIdx.x;
    const int lk = tid & 31, lr = tid >> 5;
    const int jB = (blockIdx.x >> 2) * 16;
#pragma unroll 4
    for (int kc16 = 0; kc16 < 16; kc16++) {
#pragma unroll
        for (int i = 0; i < 6; i++) {
            int r = lr + 8 * i, g = r >> 4, j = r & 15;
            float w = Whh[(size_t)(g * HH + jB + j) * HH + (kc16 << 5) + lk];
            if (g < 2) Wpc[kc16][lk][(j >> 1) * 4 + 2 * g + (j & 1)] = w;
            else       Wqc[kc16][lk][j] = w;
        }
    }
    __syncthreads();
}

// ---------------- GRU step: 128 tiles of 64b x 16j x 3 gates ---------------
// FMA chains bitwise identical to rounds 8/11: per (b,j,gate) accumulate
// X@Wih k=0..511 (streamed) then H@Whh k=0..511 (cached W).
template <bool ENC>
__device__ void gru_step(
    int s, const int* __restrict__ iseq, const float* __restrict__ eemb,
    const float* __restrict__ Xv,
    const float* __restrict__ Hin, float* __restrict__ Hout,
    float* __restrict__ eout,
    const float* __restrict__ Wih,
    const float* __restrict__ bih, const float* __restrict__ bhh,
    const int* __restrict__ ilen) {

    float (*As2)[32][132] = (float (*)[32][132])raw;
    float (*Wps)[32][36]  = (float (*)[32][36])(raw + OFF_WPS);
    float (*Wqs)[32][18]  = (float (*)[32][18])(raw + OFF_WQS);
    int* tokS             = (int*)(raw + OFF_TOK);

    const int tid = threadIdx.x;
    const int lk = tid & 31, lr = tid >> 5;       // loader coords
    const int tx = tid & 7;                       // j-pair
    const int bB = (blockIdx.x & 3) * 64;
    const int jB = (blockIdx.x >> 2) * 16;

    if (ENC) {
        if (tid < 64) tokS[tid] = iseq[s * BB + bB + tid];
    }
    __syncthreads();

    unsigned long long ar2[2]  = {0ull, 0ull};
    unsigned long long az2[2]  = {0ull, 0ull};
    unsigned long long ani2[2] = {0ull, 0ull};
    unsigned long long anh2[2] = {0ull, 0ull};

    float av[8], wv[6];

    auto ldA = [&](int ph, int kc) {
        if (ph == 0) {
            if (ENC) {
#pragma unroll
                for (int i = 0; i < 8; i++)
                    av[i] = eemb[(size_t)tokS[lr + 8 * i] * HH + kc + lk];
            } else {
#pragma unroll
                for (int i = 0; i < 8; i++)
                    av[i] = Xv[(size_t)(bB + lr + 8 * i) * HH + kc + lk];
            }
        } else {
#pragma unroll
            for (int i = 0; i < 8; i++)
                av[i] = Hin[(size_t)(bB + lr + 8 * i) * HH + kc + lk];
        }
    };
    auto ldW = [&](int kc) {   // Wih only (Whh is cached)
#pragma unroll
        for (int i = 0; i < 6; i++) {
            int r = lr + 8 * i;                   // 0..47
            int g = r >> 4, j = r & 15;
            wv[i] = Wih[(size_t)(g * HH + jB + j) * HH + kc + lk];
        }
    };
    auto stbA = [&](int buf) {
#pragma unroll
        for (int i = 0; i < 8; i++)
            *(float2*)&As2[buf][lk][2 * (lr + 8 * i)] = make_float2(av[i], av[i]);
    };
    auto stbW = [&](int buf) {
#pragma unroll
        for (int i = 0; i < 6; i++) {
            int r = lr + 8 * i;
            int g = r >> 4, j = r & 15;
            if (g < 2)
                Wps[buf][lk][(j >> 1) * 4 + 2 * g + (j & 1)] = wv[i];
            else
                Wqs[buf][lk][j] = wv[i];
        }
    };

#define GRU_INNER(AN, WP, WQ)                                                  \
    _Pragma("unroll")                                                          \
    for (int kk = 0; kk < 32; kk++) {                                          \
        ulonglong2 a2  = *(const ulonglong2*)&As2[buf][kk][(tid >> 3) * 4];    \
        ulonglong2 w01 = *(const ulonglong2*)((WP) + kk * 36 + tx * 4);        \
        unsigned long long w2 =                                                \
            *(const unsigned long long*)((WQ) + kk * 18 + tx * 2);             \
        FMA2(ar2[0], a2.x, w01.x); FMA2(ar2[1], a2.y, w01.x);                  \
        FMA2(az2[0], a2.x, w01.y); FMA2(az2[1], a2.y, w01.y);                  \
        FMA2(AN[0],  a2.x, w2);    FMA2(AN[1],  a2.y, w2);                     \
    }

    // prologue: chunk 0 (Wih phase)
    ldA(0, 0); ldW(0); stbA(0); stbW(0);
    __syncthreads();

    for (int c = 0; c < 32; c++) {
        const int buf = c & 1;
        if (c < 31) {
            const int nc = c + 1;
            ldA(nc >> 4, (nc & 15) << 5);
            if (nc < 16) ldW(nc << 5);
        }
        const float* wp = (c < 16) ? &Wps[buf][0][0]
                                   : (const float*)(raw + OFF_WPC) + (c - 16) * (32 * 36);
        const float* wq = (c < 16) ? &Wqs[buf][0][0]
                                   : (const float*)(raw + OFF_WQC) + (c - 16) * (32 * 18);
        if (c < 16) { GRU_INNER(ani2, wp, wq) } else { GRU_INNER(anh2, wp, wq) }
        if (c < 31) {
            stbA(buf ^ 1);
            if (c + 1 < 16) stbW(buf ^ 1);
        }
        __syncthreads();
    }
#undef GRU_INNER

    float2 arf[2]  = {u2f2(ar2[0]), u2f2(ar2[1])};
    float2 azf[2]  = {u2f2(az2[0]), u2f2(az2[1])};
    float2 anif[2] = {u2f2(ani2[0]), u2f2(ani2[1])};
    float2 anhf[2] = {u2f2(anh2[0]), u2f2(anh2[1])};

    const int ty = tid >> 3;
#pragma unroll
    for (int r = 0; r < 2; r++) {
        int b = bB + ty * 2 + r;
#pragma unroll
        for (int l = 0; l < 2; l++) {
            int j = jB + tx * 2 + l;
            float ar  = l ? arf[r].y  : arf[r].x;
            float az  = l ? azf[r].y  : azf[r].x;
            float ani = l ? anif[r].y : anif[r].x;
            float anh = l ? anhf[r].y : anhf[r].x;
            float rr = 1.f / (1.f + expf(-(ar + bih[j] + bhh[j])));
            float zz = 1.f / (1.f + expf(-(az + bih[HH + j] + bhh[HH + j])));
            float nn = tanhf(ani + bih[2 * HH + j] + rr * (anh + bhh[2 * HH + j]));
            float hp = Hin[b * HH + j];
            float hnew = (1.f - zz) * nn + zz * hp;
            if (ENC) {
                bool m = s < ilen[b];
                float ho = m ? hnew : hp;
                Hout[b * HH + j] = ho;
                eout[b * HH + j] = m ? ho : 0.f;
            } else {
                Hout[b * HH + j] = hnew;
            }
        }
    }
}

// ---------------- 32b x (32*JW)n GEMM core, K=512, double-buffered ----------
// (round-11 proven version)
template <int JW>
__device__ __forceinline__ void gemm_core(
    const float* const* pA, const float* const* pB,
    unsigned long long (&acc)[2][JW]) {
    float (*As2)[32][68] = (float (*)[32][68])raw;             // 17408 B
    const int BW = (JW == 2) ? 68 : 34;
    float* Bs = (float*)(raw + 17408);
    const int tid = threadIdx.x;
    const int lk = tid & 31, lr = tid >> 5;
    const int tx = tid & 15, ty = tid >> 4;
    float av[4], bv[4 * JW];
    auto ld = [&](int kc) {
#pragma unroll
        for (int i = 0; i < 4; i++) av[i] = pA[i][kc + lk];
#pragma unroll
        for (int i = 0; i < 4 * JW; i++) bv[i] = pB[i][kc + lk];
    };
    auto st = [&](int buf) {
#pragma unroll
        for (int i = 0; i < 4; i++)
            *(float2*)&As2[buf][lk][2 * (lr + 8 * i)] = make_float2(av[i], av[i]);
#pragma unroll
        for (int i = 0; i < 4 * JW; i++)
            Bs[(buf * 32 + lk) * BW + lr + 8 * i] = bv[i];
    };
    ld(0); st(0);
    __syncthreads();
    for (int c = 0; c < 16; c++) {
        const int buf = c & 1;
        if (c < 15) ld((c + 1) * 32);
#pragma unroll
        for (int kk = 0; kk < 32; kk++) {
            ulonglong2 a2 = *(const ulonglong2*)&As2[buf][kk][ty * 4];
            if (JW == 2) {
                ulonglong2 wq = *(const ulonglong2*)&Bs[(buf * 32 + kk) * BW + tx * 4];
                FMA2(acc[0][0], a2.x, wq.x);
                FMA2(acc[1][0], a2.y, wq.x);
                FMA2(acc[0][JW - 1], a2.x, wq.y);
                FMA2(acc[1][JW - 1], a2.y, wq.y);
            } else {
                unsigned long long wq =
                    *(const unsigned long long*)&Bs[(buf * 32 + kk) * BW + tx * 2];
                FMA2(acc[0][0], a2.x, wq);
                FMA2(acc[1][0], a2.y, wq);
            }
        }
        if (c < 15) st(buf ^ 1);
        __syncthreads();
    }
}

// ---------------- qpre: de @ mlpW[:, :512]^T ----------------
__device__ void qpre_phase(const int* __restrict__ tseq,
                           const float* __restrict__ demb,
                           const float* __restrict__ mlpW) {
    const int tid = threadIdx.x;
    const int lr = tid >> 5;
    const int tx = tid & 15, ty = tid >> 4;
    for (int tile = blockIdx.x; tile < 12800; tile += NB) {
        int rowt = tile >> 3, nt = tile & 7;
        int r0 = rowt * 32, n0 = nt * 64;
        const float* pA[4];
        const float* pB[8];
#pragma unroll
        for (int i = 0; i < 4; i++) {
            int r = r0 + lr + 8 * i;
            int t = r >> 8, b = r & 255;
            int tok = (t == 0) ? 1 : tseq[(t - 1) * BB + b];
            pA[i] = demb + (size_t)tok * HH;
        }
#pragma unroll
        for (int i = 0; i < 8; i++)
            pB[i] = mlpW + (size_t)(n0 + lr + 8 * i) * 1024;
        unsigned long long acc[2][2] = {{0ull, 0ull}, {0ull, 0ull}};
        gemm_core<2>(pA, pB, acc);
#pragma unroll
        for (int r = 0; r < 2; r++) {
            int row = r0 + ty * 2 + r;
#pragma unroll
            for (int p = 0; p < 2; p++) {
                float2 v = u2f2(acc[r][p]);
                *(float2*)&g_qpre[(size_t)row * HH + n0 + tx * 4 + 2 * p] = v;
            }
        }
        __syncthreads();
    }
}

// ---------------- mlp ctx half: acc starts at qpre, k=512..1023 -------------
__device__ void mlp_phase(int t, const float* __restrict__ mlpW,
                          const float* __restrict__ mlpb) {
    const int tid = threadIdx.x;
    const int lr = tid >> 5;
    const int tx = tid & 15, ty = tid >> 4;
    const int bB = (blockIdx.x & 7) * 32, n0 = (blockIdx.x >> 3) * 32;
    const float* pA[4];
    const float* pB[4];
#pragma unroll
    for (int i = 0; i < 4; i++) {
        pA[i] = g_ctx + (size_t)(bB + lr + 8 * i) * HH;
        pB[i] = mlpW + (size_t)(n0 + lr + 8 * i) * 1024 + 512;
    }
    unsigned long long acc[2][1];
#pragma unroll
    for (int r = 0; r < 2; r++)
        acc[r][0] = *(const unsigned long long*)
            &g_qpre[(size_t)(t * BB + bB + ty * 2 + r) * HH + n0 + tx * 2];
    gemm_core<1>(pA, pB, acc);
#pragma unroll
    for (int r = 0; r < 2; r++) {
        int b = bB + ty * 2 + r;
        float2 v = u2f2(acc[r][0]);
        int j0 = n0 + tx * 2;
        g_xv[b * HH + j0]     = tanhf(v.x + mlpb[j0]);
        g_xv[b * HH + j0 + 1] = tanhf(v.y + mlpb[j0 + 1]);
    }
}

// ---------------- fused logits(t) + ah(t+1): N=1024, full-K sequential ------
__device__ void logah_phase(const float* __restrict__ h,
                            const float* __restrict__ outW,
                            const float* __restrict__ attW,
                            const float* __restrict__ outb,
                            const float* __restrict__ attb) {
    const int tid = threadIdx.x;
    const int lr = tid >> 5;
    const int tx = tid & 15, ty = tid >> 4;
    const int bB = (blockIdx.x & 7) * 32, n0 = (blockIdx.x >> 3) * 64;
    const float* pA[4];
    const float* pB[8];
#pragma unroll
    for (int i = 0; i < 4; i++)
        pA[i] = h + (size_t)(bB + lr + 8 * i) * HH;
#pragma unroll
    for (int i = 0; i < 8; i++) {
        int n = n0 + lr + 8 * i;
        pB[i] = (n < 512) ? outW + (size_t)n * HH : attW + (size_t)(n - 512) * HH;
    }
    unsigned long long acc[2][2] = {{0ull, 0ull}, {0ull, 0ull}};
    gemm_core<2>(pA, pB, acc);
#pragma unroll
    for (int r = 0; r < 2; r++) {
        int b = bB + ty * 2 + r;
#pragma unroll
        for (int p = 0; p < 2; p++) {
            float2 v = u2f2(acc[r][p]);
#pragma unroll
            for (int l = 0; l < 2; l++) {
                int n = n0 + tx * 4 + 2 * p + l;
                float val = l ? v.y : v.x;
                if (n < 512)
                    g_logits[b * VV + n] = val + outb[n];
                else
                    g_ah[b * HH + n - 512] = fmaxf(val + attb[n - 512], 0.f);
            }
        }
    }
}

// ---------------- attention (numerics unchanged since round 2) --------------
__device__ void attn_one(int b) {
    float* ah   = (float*)raw;
    float* wm   = ah + 512;
    float* wsum = wm + 8;
    float* wctx = wsum + 8;

    const int tid = threadIdx.x, warp = tid >> 5, lane = tid & 31;
    ah[tid]       = g_ah[b * HH + tid];
    ah[tid + 256] = g_ah[b * HH + tid + 256];
    __syncthreads();

    float ahr[16];
#pragma unroll
    for (int i = 0; i < 16; i++) ahr[i] = ah[lane + 32 * i];

    float m = -1e30f, s = 0.f;
    float ctx[16];
#pragma unroll
    for (int i = 0; i < 16; i++) ctx[i] = 0.f;

    for (int sI = warp; sI < SB; sI += 8) {
        const float* eo = g_eo + ((size_t)sI * BB + b) * HH;
        float ev[16], d = 0.f;
#pragma unroll
        for (int i = 0; i < 16; i++) { ev[i] = eo[lane + 32 * i]; d += ev[i] * ahr[i]; }
#pragma unroll
        for (int o = 16; o > 0; o >>= 1) d += __shfl_xor_sync(0xffffffffu, d, o);
        float mn = fmaxf(m, d);
        float sc = expf(m - mn);
        float p  = expf(d - mn);
        s = s * sc + p;
#pragma unroll
        for (int i = 0; i < 16; i++) ctx[i] = ctx[i] * sc + p * ev[i];
        m = mn;
    }
    if (lane == 0) { wm[warp] = m; wsum[warp] = s; }
#pragma unroll
    for (int i = 0; i < 16; i++) wctx[warp * 512 + lane + 32 * i] = ctx[i];
    __syncthreads();

    float M = -1e30f;
#pragma unroll
    for (int w = 0; w < 8; w++) M = fmaxf(M, wm[w]);
    float S = 0.f, esc[8];
#pragma unroll
    for (int w = 0; w < 8; w++) { esc[w] = expf(wm[w] - M); S += wsum[w] * esc[w]; }
    float inv = 1.f / S;
#pragma unroll
    for (int hh = 0; hh < 2; hh++) {
        int h = tid + hh * 256;
        float acc = 0.f;
#pragma unroll
        for (int w = 0; w < 8; w++) acc += esc[w] * wctx[w * 512 + h];
        g_ctx[b * HH + h] = acc * inv;
    }
    __syncthreads();
}

// ---------------- output softmax/argmax/loss (numerics unchanged) -----------
__device__ void out_one(int t, int b, const int* __restrict__ tseq,
                        float* __restrict__ dout) {
    float* sv = (float*)raw;
    int*   si = (int*)(raw + 1024);
    const int tid = threadIdx.x;
    const float* lrow = g_logits + b * VV;
    float v0 = lrow[tid], v1 = lrow[tid + 256];
    float mv; int mi;
    if (v0 >= v1) { mv = v0; mi = tid; } else { mv = v1; mi = tid + 256; }
    sv[tid] = mv; si[tid] = mi;
    __syncthreads();
    for (int o = 128; o > 0; o >>= 1) {
        if (tid < o) {
            float ov = sv[tid + o]; int oi = si[tid + o];
            if (ov > sv[tid] || (ov == sv[tid] && oi < si[tid])) { sv[tid] = ov; si[tid] = oi; }
        }
        __syncthreads();
    }
    float bmax = sv[0];
    int pred = si[0];
    __syncthreads();
    sv[tid] = expf(v0 - bmax) + expf(v1 - bmax);
    __syncthreads();
    for (int o = 128; o > 0; o >>= 1) {
        if (tid < o) sv[tid] += sv[tid + o];
        __syncthreads();
    }
    if (tid == 0) {
        int tgt = tseq[t * BB + b];
        float p = expf(lrow[tgt] - bmax) / sv[0];
        p = fmaxf(p, 1e-10f);
        g_loss_tb[t * BB + b] = -logf(p);
        dout[t * BB + b] = (float)pred;
    }
    __syncthreads();
}

// ---------------- persistent mega-kernel ----------------
__global__ void __launch_bounds__(NT) k_mega(
    const int* __restrict__ iseq, const int* __restrict__ ilen,
    const int* __restrict__ tseq,
    const float* __restrict__ eemb,
    const float* __restrict__ eWih, const float* __restrict__ eWhh,
    const float* __restrict__ ebih, const float* __restrict__ ebhh,
    const float* __restrict__ attW, const float* __restrict__ attb,
    const float* __restrict__ demb,
    const float* __restrict__ dWih, const float* __restrict__ dWhh,
    const float* __restrict__ dbih, const float* __restrict__ dbhh,
    const float* __restrict__ mlpW, const float* __restrict__ mlpb,
    const float* __restrict__ outW, const float* __restrict__ outb,
    float* __restrict__ dout) {

    const int bid = blockIdx.x, tid = threadIdx.x;

    for (int i = bid * NT + tid; i < BB * HH; i += NB * NT) g_h[0][i] = 0.f;
    gsync();

    qpre_phase(tseq, demb, mlpW);
    gsync();

    // encoder: cache eWhh tile once, then 200 steps
    load_whh_cache(eWhh);
    for (int s = 0; s < SB; s++) {
        int pin = s & 1;
        gru_step<true>(s, iseq, eemb, nullptr, g_h[pin], g_h[pin ^ 1],
                       g_eo + (size_t)s * BB * HH,
                       eWih, ebih, ebhh, ilen);
        gsync();
    }

    // ah for t=0 (logits half junk, never read)
    logah_phase(g_h[0], outW, attW, outb, attb);
    gsync();

    // decoder: cache dWhh tile once, then 200 steps, 4 barriers each
    load_whh_cache(dWhh);
    for (int t = 0; t < TB; t++) {
        int pin = t & 1;
        if (t > 0) {
            out_one(t - 1, bid * 2 + 0, tseq, dout);
            out_one(t - 1, bid * 2 + 1, tseq, dout);
        }
        attn_one(bid * 2 + 0);
        attn_one(bid * 2 + 1);
        gsync();
        mlp_phase(t, mlpW, mlpb);
        gsync();
        gru_step<false>(0, nullptr, nullptr, g_xv, g_h[pin], g_h[pin ^ 1],
                        nullptr, dWih, dbih, dbhh, nullptr);
        gsync();
        logah_phase(g_h[pin ^ 1], outW, attW, outb, attb);
        gsync();
    }
    out_one(TB - 1, bid * 2 + 0, tseq, dout);
    out_one(TB - 1, bid * 2 + 1, tseq, dout);
    gsync();

    if (bid != 0) return;
    {
        float* sf = (float*)raw;
        int*   sc = (int*)(raw + 1024);
        int*   sa = (int*)(raw + 2048);
        float ls = 0.f; int corr = 0;
        for (int i = tid; i < TB * BB; i += NT) {
            ls += g_loss_tb[i];
            corr += (dout[i] == (float)tseq[i]) ? 1 : 0;
        }
        int allc = 1;
        for (int t = 0; t < TB; t++)
            if (dout[t * BB + tid] != (float)tseq[t * BB + tid]) { allc = 0; break; }
        sf[tid] = ls; sc[tid] = corr; sa[tid] = allc;
        __syncthreads();
        for (int o = 128; o > 0; o >>= 1) {
            if (tid < o) { sf[tid] += sf[tid + o]; sc[tid] += sc[tid + o]; sa[tid] += sa[tid + o]; }
            __syncthreads();
        }
        if (tid == 0) {
            dout[TB * BB]     = sf[0] / (float)(TB * BB);
            dout[TB * BB + 1] = (float)sa[0] / (float)BB;
            dout[TB * BB + 2] = (float)sc[0] / (float)(TB * BB);
        }
    }
}

// ---------------- host ----------------
extern "C" void kernel_launch(void* const* d_in, const int* in_sizes, int n_in,
                              void* d_out, int out_size) {
    (void)in_sizes; (void)n_in; (void)out_size;
    cudaFuncSetAttribute(k_mega, cudaFuncAttributeMaxDynamicSharedMemorySize,
                         SMEM_BYTES);
    k_mega<<<NB, NT, SMEM_BYTES>>>(
        (const int*)d_in[0], (const int*)d_in[1], (const int*)d_in[2],
        (const float*)d_in[3], (const float*)d_in[4], (const float*)d_in[5],
        (const float*)d_in[6], (const float*)d_in[7], (const float*)d_in[8],
        (const float*)d_in[9], (const float*)d_in[10], (const float*)d_in[11],
        (const float*)d_in[12], (const float*)d_in[13], (const float*)d_in[14],
        (const float*)d_in[15], (const float*)d_in[16], (const float*)d_in[17],
        (const float*)d_in[18], (float*)d_out);
}

// round 17
// speedup vs baseline: 1.0578x; 1.0182x over previous
#include <cuda_runtime.h>
#include <math.h>

#define SB 200
#define TB 200
#define BB 256
#define HH 512
#define VV 512
#define NB 128    // persistent blocks, all co-resident (1 per SM)
#define NT 256

// ---------------- device scratch ----------------
// g_eo rows are stored TRANSPOSED: element h of row (s,b) lives at offset
// (h&31)*16 + (h>>5). Only the encoder epilogue writes it and attn reads it.
__device__ float g_eo[SB * BB * HH];
__device__ float g_qpre[TB * BB * HH];    // de @ mlpW[:, :512]^T
__device__ float g_h[2][BB * HH];         // hidden ping-pong
__device__ float g_xv[BB * HH];           // decoder GRU input x
__device__ float g_ctx[BB * HH];          // attention context
__device__ float g_ah[BB * HH];           // relu(h @ att_W^T + att_b)
__device__ float g_logits[BB * VV];       // logits (bias included)
__device__ float g_loss_tb[TB * BB];

// ---------------- grid barrier (flat, proven) -------------------------------
__device__ unsigned g_cnt = 0;
__device__ volatile unsigned g_gen = 0;

__device__ __forceinline__ void gsync() {
    __syncthreads();
    if (threadIdx.x == 0) {
        __threadfence();
        unsigned gen = g_gen;
        if (atomicAdd(&g_cnt, 1u) == NB - 1) {
            g_cnt = 0;
            __threadfence();
            g_gen = gen + 1;
        } else {
            while (g_gen == gen) { }
        }
        __threadfence();
    }
    __syncthreads();
}

// ---------------- shared memory layout (dynamic) ----------------
#define OFF_WPS 33792
#define OFF_WQS 43008
#define OFF_TOK 47616
#define OFF_WPC 48128
#define OFF_WQC 121856
#define SMEM_BYTES 158720

extern __shared__ char raw[];

#define FMA2(acc, a, b) \
    asm("fma.rn.f32x2 %0, %1, %2, %0;" : "+l"(acc) : "l"(a), "l"(b))

__device__ __forceinline__ float2 u2f2(unsigned long long v) {
    float2 r;
    asm("mov.b64 {%0, %1}, %2;" : "=f"(r.x), "=f"(r.y) : "l"(v));
    return r;
}

// ---------------- load this block's Whh tile into the persistent cache -----
__device__ void load_whh_cache(const float* __restrict__ Whh) {
    float (*Wpc)[32][36] = (float (*)[32][36])(raw + OFF_WPC);
    float (*Wqc)[32][18] = (float (*)[32][18])(raw + OFF_WQC);
    const int tid = threadIdx.x;
    const int lk = tid & 31, lr = tid >> 5;
    const int jB = (blockIdx.x >> 2) * 16;
#pragma unroll 4
    for (int kc16 = 0; kc16 < 16; kc16++) {
#pragma unroll
        for (int i = 0; i < 6; i++) {
            int r = lr + 8 * i, g = r >> 4, j = r & 15;
            float w = Whh[(size_t)(g * HH + jB + j) * HH + (kc16 << 5) + lk];
            if (g < 2) Wpc[kc16][lk][(j >> 1) * 4 + 2 * g + (j & 1)] = w;
            else       Wqc[kc16][lk][j] = w;
        }
    }
    __syncthreads();
}

// ---------------- GRU step: 128 tiles of 64b x 16j x 3 gates ---------------
// FMA chains bitwise identical to rounds 8/11.
template <bool ENC>
__device__ void gru_step(
    int s, const int* __restrict__ iseq, const float* __restrict__ eemb,
    const float* __restrict__ Xv,
    const float* __restrict__ Hin, float* __restrict__ Hout,
    float* __restrict__ eout,
    const float* __restrict__ Wih,
    const float* __restrict__ bih, const float* __restrict__ bhh,
    const int* __restrict__ ilen) {

    float (*As2)[32][132] = (float (*)[32][132])raw;
    float (*Wps)[32][36]  = (float (*)[32][36])(raw + OFF_WPS);
    float (*Wqs)[32][18]  = (float (*)[32][18])(raw + OFF_WQS);
    int* tokS             = (int*)(raw + OFF_TOK);

    const int tid = threadIdx.x;
    const int lk = tid & 31, lr = tid >> 5;
    const int tx = tid & 7;
    const int bB = (blockIdx.x & 3) * 64;
    const int jB = (blockIdx.x >> 2) * 16;

    if (ENC) {
        if (tid < 64) tokS[tid] = iseq[s * BB + bB + tid];
    }
    __syncthreads();

    unsigned long long ar2[2]  = {0ull, 0ull};
    unsigned long long az2[2]  = {0ull, 0ull};
    unsigned long long ani2[2] = {0ull, 0ull};
    unsigned long long anh2[2] = {0ull, 0ull};

    float av[8], wv[6];

    auto ldA = [&](int ph, int kc) {
        if (ph == 0) {
            if (ENC) {
#pragma unroll
                for (int i = 0; i < 8; i++)
                    av[i] = eemb[(size_t)tokS[lr + 8 * i] * HH + kc + lk];
            } else {
#pragma unroll
                for (int i = 0; i < 8; i++)
                    av[i] = Xv[(size_t)(bB + lr + 8 * i) * HH + kc + lk];
            }
        } else {
#pragma unroll
            for (int i = 0; i < 8; i++)
                av[i] = Hin[(size_t)(bB + lr + 8 * i) * HH + kc + lk];
        }
    };
    auto ldW = [&](int kc) {
#pragma unroll
        for (int i = 0; i < 6; i++) {
            int r = lr + 8 * i;
            int g = r >> 4, j = r & 15;
            wv[i] = Wih[(size_t)(g * HH + jB + j) * HH + kc + lk];
        }
    };
    auto stbA = [&](int buf) {
#pragma unroll
        for (int i = 0; i < 8; i++)
            *(float2*)&As2[buf][lk][2 * (lr + 8 * i)] = make_float2(av[i], av[i]);
    };
    auto stbW = [&](int buf) {
#pragma unroll
        for (int i = 0; i < 6; i++) {
            int r = lr + 8 * i;
            int g = r >> 4, j = r & 15;
            if (g < 2)
                Wps[buf][lk][(j >> 1) * 4 + 2 * g + (j & 1)] = wv[i];
            else
                Wqs[buf][lk][j] = wv[i];
        }
    };

#define GRU_INNER(AN, WP, WQ)                                                  \
    _Pragma("unroll")                                                          \
    for (int kk = 0; kk < 32; kk++) {                                          \
        ulonglong2 a2  = *(const ulonglong2*)&As2[buf][kk][(tid >> 3) * 4];    \
        ulonglong2 w01 = *(const ulonglong2*)((WP) + kk * 36 + tx * 4);        \
        unsigned long long w2 =                                                \
            *(const unsigned long long*)((WQ) + kk * 18 + tx * 2);             \
        FMA2(ar2[0], a2.x, w01.x); FMA2(ar2[1], a2.y, w01.x);                  \
        FMA2(az2[0], a2.x, w01.y); FMA2(az2[1], a2.y, w01.y);                  \
        FMA2(AN[0],  a2.x, w2);    FMA2(AN[1],  a2.y, w2);                     \
    }

    ldA(0, 0); ldW(0); stbA(0); stbW(0);
    __syncthreads();

    for (int c = 0; c < 32; c++) {
        const int buf = c & 1;
        if (c < 31) {
            const int nc = c + 1;
            ldA(nc >> 4, (nc & 15) << 5);
            if (nc < 16) ldW(nc << 5);
        }
        const float* wp = (c < 16) ? &Wps[buf][0][0]
                                   : (const float*)(raw + OFF_WPC) + (c - 16) * (32 * 36);
        const float* wq = (c < 16) ? &Wqs[buf][0][0]
                                   : (const float*)(raw + OFF_WQC) + (c - 16) * (32 * 18);
        if (c < 16) { GRU_INNER(ani2, wp, wq) } else { GRU_INNER(anh2, wp, wq) }
        if (c < 31) {
            stbA(buf ^ 1);
            if (c + 1 < 16) stbW(buf ^ 1);
        }
        __syncthreads();
    }
#undef GRU_INNER

    float2 arf[2]  = {u2f2(ar2[0]), u2f2(ar2[1])};
    float2 azf[2]  = {u2f2(az2[0]), u2f2(az2[1])};
    float2 anif[2] = {u2f2(ani2[0]), u2f2(ani2[1])};
    float2 anhf[2] = {u2f2(anh2[0]), u2f2(anh2[1])};

    const int ty = tid >> 3;
#pragma unroll
    for (int r = 0; r < 2; r++) {
        int b = bB + ty * 2 + r;
#pragma unroll
        for (int l = 0; l < 2; l++) {
            int j = jB + tx * 2 + l;
            float ar  = l ? arf[r].y  : arf[r].x;
            float az  = l ? azf[r].y  : azf[r].x;
            float ani = l ? anif[r].y : anif[r].x;
            float anh = l ? anhf[r].y : anhf[r].x;
            float rr = 1.f / (1.f + expf(-(ar + bih[j] + bhh[j])));
            float zz = 1.f / (1.f + expf(-(az + bih[HH + j] + bhh[HH + j])));
            float nn = tanhf(ani + bih[2 * HH + j] + rr * (anh + bhh[2 * HH + j]));
            float hp = Hin[b * HH + j];
            float hnew = (1.f - zz) * nn + zz * hp;
            if (ENC) {
                bool m = s < ilen[b];
                float ho = m ? hnew : hp;
                Hout[b * HH + j] = ho;
                // transposed eo layout: element j -> (j&31)*16 + (j>>5)
                eout[b * HH + ((j & 31) * 16 + (j >> 5))] = m ? ho : 0.f;
            } else {
                Hout[b * HH + j] = hnew;
            }
        }
    }
}

// ---------------- 32b x (32*JW)n GEMM core, K=512, double-buffered ----------
template <int JW>
__device__ __forceinline__ void gemm_core(
    const float* const* pA, const float* const* pB,
    unsigned long long (&acc)[2][JW]) {
    float (*As2)[32][68] = (float (*)[32][68])raw;
    const int BW = (JW == 2) ? 68 : 34;
    float* Bs = (float*)(raw + 17408);
    const int tid = threadIdx.x;
    const int lk = tid & 31, lr = tid >> 5;
    const int tx = tid & 15, ty = tid >> 4;
    float av[4], bv[4 * JW];
    auto ld = [&](int kc) {
#pragma unroll
        for (int i = 0; i < 4; i++) av[i] = pA[i][kc + lk];
#pragma unroll
        for (int i = 0; i < 4 * JW; i++) bv[i] = pB[i][kc + lk];
    };
    auto st = [&](int buf) {
#pragma unroll
        for (int i = 0; i < 4; i++)
            *(float2*)&As2[buf][lk][2 * (lr + 8 * i)] = make_float2(av[i], av[i]);
#pragma unroll
        for (int i = 0; i < 4 * JW; i++)
            Bs[(buf * 32 + lk) * BW + lr + 8 * i] = bv[i];
    };
    ld(0); st(0);
    __syncthreads();
    for (int c = 0; c < 16; c++) {
        const int buf = c & 1;
        if (c < 15) ld((c + 1) * 32);
#pragma unroll
        for (int kk = 0; kk < 32; kk++) {
            ulonglong2 a2 = *(const ulonglong2*)&As2[buf][kk][ty * 4];
            if (JW == 2) {
                ulonglong2 wq = *(const ulonglong2*)&Bs[(buf * 32 + kk) * BW + tx * 4];
                FMA2(acc[0][0], a2.x, wq.x);
                FMA2(acc[1][0], a2.y, wq.x);
                FMA2(acc[0][JW - 1], a2.x, wq.y);
                FMA2(acc[1][JW - 1], a2.y, wq.y);
            } else {
                unsigned long long wq =
                    *(const unsigned long long*)&Bs[(buf * 32 + kk) * BW + tx * 2];
                FMA2(acc[0][0], a2.x, wq);
                FMA2(acc[1][0], a2.y, wq);
            }
        }
        if (c < 15) st(buf ^ 1);
        __syncthreads();
    }
}

// ---------------- qpre: de @ mlpW[:, :512]^T ----------------
__device__ void qpre_phase(const int* __restrict__ tseq,
                           const float* __restrict__ demb,
                           const float* __restrict__ mlpW) {
    const int tid = threadIdx.x;
    const int lr = tid >> 5;
    const int tx = tid & 15, ty = tid >> 4;
    for (int tile = blockIdx.x; tile < 12800; tile += NB) {
        int rowt = tile >> 3, nt = tile & 7;
        int r0 = rowt * 32, n0 = nt * 64;
        const float* pA[4];
        const float* pB[8];
#pragma unroll
        for (int i = 0; i < 4; i++) {
            int r = r0 + lr + 8 * i;
            int t = r >> 8, b = r & 255;
            int tok = (t == 0) ? 1 : tseq[(t - 1) * BB + b];
            pA[i] = demb + (size_t)tok * HH;
        }
#pragma unroll
        for (int i = 0; i < 8; i++)
            pB[i] = mlpW + (size_t)(n0 + lr + 8 * i) * 1024;
        unsigned long long acc[2][2] = {{0ull, 0ull}, {0ull, 0ull}};
        gemm_core<2>(pA, pB, acc);
#pragma unroll
        for (int r = 0; r < 2; r++) {
            int row = r0 + ty * 2 + r;
#pragma unroll
            for (int p = 0; p < 2; p++) {
                float2 v = u2f2(acc[r][p]);
                *(float2*)&g_qpre[(size_t)row * HH + n0 + tx * 4 + 2 * p] = v;
            }
        }
        __syncthreads();
    }
}

// ---------------- mlp ctx half: acc starts at qpre, k=512..1023 -------------
__device__ void mlp_phase(int t, const float* __restrict__ mlpW,
                          const float* __restrict__ mlpb) {
    const int tid = threadIdx.x;
    const int lr = tid >> 5;
    const int tx = tid & 15, ty = tid >> 4;
    const int bB = (blockIdx.x & 7) * 32, n0 = (blockIdx.x >> 3) * 32;
    const float* pA[4];
    const float* pB[4];
#pragma unroll
    for (int i = 0; i < 4; i++) {
        pA[i] = g_ctx + (size_t)(bB + lr + 8 * i) * HH;
        pB[i] = mlpW + (size_t)(n0 + lr + 8 * i) * 1024 + 512;
    }
    unsigned long long acc[2][1];
#pragma unroll
    for (int r = 0; r < 2; r++)
        acc[r][0] = *(const unsigned long long*)
            &g_qpre[(size_t)(t * BB + bB + ty * 2 + r) * HH + n0 + tx * 2];
    gemm_core<1>(pA, pB, acc);
#pragma unroll
    for (int r = 0; r < 2; r++) {
        int b = bB + ty * 2 + r;
        float2 v = u2f2(acc[r][0]);
        int j0 = n0 + tx * 2;
        g_xv[b * HH + j0]     = tanhf(v.x + mlpb[j0]);
        g_xv[b * HH + j0 + 1] = tanhf(v.y + mlpb[j0 + 1]);
    }
}

// ---------------- fused logits(t) + ah(t+1): N=1024, full-K sequential ------
__device__ void logah_phase(const float* __restrict__ h,
                            const float* __restrict__ outW,
                            const float* __restrict__ attW,
                            const float* __restrict__ outb,
                            const float* __restrict__ attb) {
    const int tid = threadIdx.x;
    const int lr = tid >> 5;
    const int tx = tid & 15, ty = tid >> 4;
    const int bB = (blockIdx.x & 7) * 32, n0 = (blockIdx.x >> 3) * 64;
    const float* pA[4];
    const float* pB[8];
#pragma unroll
    for (int i = 0; i < 4; i++)
        pA[i] = h + (size_t)(bB + lr + 8 * i) * HH;
#pragma unroll
    for (int i = 0; i < 8; i++) {
        int n = n0 + lr + 8 * i;
        pB[i] = (n < 512) ? outW + (size_t)n * HH : attW + (size_t)(n - 512) * HH;
    }
    unsigned long long acc[2][2] = {{0ull, 0ull}, {0ull, 0ull}};
    gemm_core<2>(pA, pB, acc);
#pragma unroll
    for (int r = 0; r < 2; r++) {
        int b = bB + ty * 2 + r;
#pragma unroll
        for (int p = 0; p < 2; p++) {
            float2 v = u2f2(acc[r][p]);
#pragma unroll
            for (int l = 0; l < 2; l++) {
                int n = n0 + tx * 4 + 2 * p + l;
                float val = l ? v.y : v.x;
                if (n < 512)
                    g_logits[b * VV + n] = val + outb[n];
                else
                    g_ah[b * HH + n - 512] = fmaxf(val + attb[n - 512], 0.f);
            }
        }
    }
}

// ---------------- attention: transposed eo reads + prefetch -----------------
// Values, lane assignment and all FMA/softmax chains identical to round 11.
__device__ void attn_one(int b) {
    float* ah   = (float*)raw;
    float* wm   = ah + 512;
    float* wsum = wm + 8;
    float* wctx = wsum + 8;

    const int tid = threadIdx.x, warp = tid >> 5, lane = tid & 31;
    ah[tid]       = g_ah[b * HH + tid];
    ah[tid + 256] = g_ah[b * HH + tid + 256];
    __syncthreads();

    float ahr[16];
#pragma unroll
    for (int i = 0; i < 16; i++) ahr[i] = ah[lane + 32 * i];

    float m = -1e30f, s = 0.f;
    float ctx[16];
#pragma unroll
    for (int i = 0; i < 16; i++) ctx[i] = 0.f;

    float ev0[16], ev1[16];
    auto ldrow = [&](int sI, float (&E)[16]) {
        const float4* p =
            (const float4*)(g_eo + ((size_t)sI * BB + b) * HH) + lane * 4;
        float4 f0 = p[0], f1 = p[1], f2 = p[2], f3 = p[3];
        E[0] = f0.x;  E[1] = f0.y;  E[2] = f0.z;  E[3] = f0.w;
        E[4] = f1.x;  E[5] = f1.y;  E[6] = f1.z;  E[7] = f1.w;
        E[8] = f2.x;  E[9] = f2.y;  E[10] = f2.z; E[11] = f2.w;
        E[12] = f3.x; E[13] = f3.y; E[14] = f3.z; E[15] = f3.w;
    };
    auto body = [&](float (&E)[16]) {
        float d = 0.f;
#pragma unroll
        for (int i = 0; i < 16; i++) d += E[i] * ahr[i];
#pragma unroll
        for (int o = 16; o > 0; o >>= 1) d += __shfl_xor_sync(0xffffffffu, d, o);
        float mn = fmaxf(m, d);
        float sc = expf(m - mn);
        float p  = expf(d - mn);
        s = s * sc + p;
#pragma unroll
        for (int i = 0; i < 16; i++) ctx[i] = ctx[i] * sc + p * E[i];
        m = mn;
    };

    // 25 rows per warp (sI = warp + 8*it), pipelined ping-pong
    ldrow(warp, ev0);
    for (int it = 0; it < 24; it += 2) {
        ldrow(warp + 8 * (it + 1), ev1);
        body(ev0);
        ldrow(warp + 8 * (it + 2), ev0);
        body(ev1);
    }
    body(ev0);   // it == 24

    if (lane == 0) { wm[warp] = m; wsum[warp] = s; }
#pragma unroll
    for (int i = 0; i < 16; i++) wctx[warp * 512 + lane + 32 * i] = ctx[i];
    __syncthreads();

    float M = -1e30f;
#pragma unroll
    for (int w = 0; w < 8; w++) M = fmaxf(M, wm[w]);
    float S = 0.f, esc[8];
#pragma unroll
    for (int w = 0; w < 8; w++) { esc[w] = expf(wm[w] - M); S += wsum[w] * esc[w]; }
    float inv = 1.f / S;
#pragma unroll
    for (int hh = 0; hh < 2; hh++) {
        int h = tid + hh * 256;
        float acc = 0.f;
#pragma unroll
        for (int w = 0; w < 8; w++) acc += esc[w] * wctx[w * 512 + h];
        g_ctx[b * HH + h] = acc * inv;
    }
    __syncthreads();
}

// ---------------- output softmax/argmax/loss (numerics unchanged) -----------
__device__ void out_one(int t, int b, const int* __restrict__ tseq,
                        float* __restrict__ dout) {
    float* sv = (float*)raw;
    int*   si = (int*)(raw + 1024);
    const int tid = threadIdx.x;
    const float* lrow = g_logits + b * VV;
    float v0 = lrow[tid], v1 = lrow[tid + 256];
    float mv; int mi;
    if (v0 >= v1) { mv = v0; mi = tid; } else { mv = v1; mi = tid + 256; }
    sv[tid] = mv; si[tid] = mi;
    __syncthreads();
    for (int o = 128; o > 0; o >>= 1) {
        if (tid < o) {
            float ov = sv[tid + o]; int oi = si[tid + o];
            if (ov > sv[tid] || (ov == sv[tid] && oi < si[tid])) { sv[tid] = ov; si[tid] = oi; }
        }
        __syncthreads();
    }
    float bmax = sv[0];
    int pred = si[0];
    __syncthreads();
    sv[tid] = expf(v0 - bmax) + expf(v1 - bmax);
    __syncthreads();
    for (int o = 128; o > 0; o >>= 1) {
        if (tid < o) sv[tid] += sv[tid + o];
        __syncthreads();
    }
    if (tid == 0) {
        int tgt = tseq[t * BB + b];
        float p = expf(lrow[tgt] - bmax) / sv[0];
        p = fmaxf(p, 1e-10f);
        g_loss_tb[t * BB + b] = -logf(p);
        dout[t * BB + b] = (float)pred;
    }
    __syncthreads();
}

// ---------------- persistent mega-kernel ----------------
__global__ void __launch_bounds__(NT) k_mega(
    const int* __restrict__ iseq, const int* __restrict__ ilen,
    const int* __restrict__ tseq,
    const float* __restrict__ eemb,
    const float* __restrict__ eWih, const float* __restrict__ eWhh,
    const float* __restrict__ ebih, const float* __restrict__ ebhh,
    const float* __restrict__ attW, const float* __restrict__ attb,
    const float* __restrict__ demb,
    const float* __restrict__ dWih, const float* __restrict__ dWhh,
    const float* __restrict__ dbih, const float* __restrict__ dbhh,
    const float* __restrict__ mlpW, const float* __restrict__ mlpb,
    const float* __restrict__ outW, const float* __restrict__ outb,
    float* __restrict__ dout) {

    const int bid = blockIdx.x, tid = threadIdx.x;

    for (int i = bid * NT + tid; i < BB * HH; i += NB * NT) g_h[0][i] = 0.f;
    gsync();

    qpre_phase(tseq, demb, mlpW);
    gsync();

    // encoder: cache eWhh tile once, then 200 steps
    load_whh_cache(eWhh);
    for (int s = 0; s < SB; s++) {
        int pin = s & 1;
        gru_step<true>(s, iseq, eemb, nullptr, g_h[pin], g_h[pin ^ 1],
                       g_eo + (size_t)s * BB * HH,
                       eWih, ebih, ebhh, ilen);
        gsync();
    }

    // ah for t=0 (logits half junk, never read)
    logah_phase(g_h[0], outW, attW, outb, attb);
    gsync();

    // decoder: cache dWhh tile once, then 200 steps, 4 barriers each
    load_whh_cache(dWhh);
    for (int t = 0; t < TB; t++) {
        int pin = t & 1;
        if (t > 0) {
            out_one(t - 1, bid * 2 + 0, tseq, dout);
            out_one(t - 1, bid * 2 + 1, tseq, dout);
        }
        attn_one(bid * 2 + 0);
        attn_one(bid * 2 + 1);
        gsync();
        mlp_phase(t, mlpW, mlpb);
        gsync();
        gru_step<false>(0, nullptr, nullptr, g_xv, g_h[pin], g_h[pin ^ 1],
                        nullptr, dWih, dbih, dbhh, nullptr);
        gsync();
        logah_phase(g_h[pin ^ 1], outW, attW, outb, attb);
        gsync();
    }
    out_one(TB - 1, bid * 2 + 0, tseq, dout);
    out_one(TB - 1, bid * 2 + 1, tseq, dout);
    gsync();

    if (bid != 0) return;
    {
        float* sf = (float*)raw;
        int*   sc = (int*)(raw + 1024);
        int*   sa = (int*)(raw + 2048);
        float ls = 0.f; int corr = 0;
        for (int i = tid; i < TB * BB; i += NT) {
            ls += g_loss_tb[i];
            corr += (dout[i] == (float)tseq[i]) ? 1 : 0;
        }
        int allc = 1;
        for (int t = 0; t < TB; t++)
            if (dout[t * BB + tid] != (float)tseq[t * BB + tid]) { allc = 0; break; }
        sf[tid] = ls; sc[tid] = corr; sa[tid] = allc;
        __syncthreads();
        for (int o = 128; o > 0; o >>= 1) {
            if (tid < o) { sf[tid] += sf[tid + o]; sc[tid] += sc[tid + o]; sa[tid] += sa[tid + o]; }
            __syncthreads();
        }
        if (tid == 0) {
            dout[TB * BB]     = sf[0] / (float)(TB * BB);
            dout[TB * BB + 1] = (float)sa[0] / (float)BB;
            dout[TB * BB + 2] = (float)sc[0] / (float)(TB * BB);
        }
    }
}

// ---------------- host ----------------
extern "C" void kernel_launch(void* const* d_in, const int* in_sizes, int n_in,
                              void* d_out, int out_size) {
    (void)in_sizes; (void)n_in; (void)out_size;
    cudaFuncSetAttribute(k_mega, cudaFuncAttributeMaxDynamicSharedMemorySize,
                         SMEM_BYTES);
    k_mega<<<NB, NT, SMEM_BYTES>>>(
        (const int*)d_in[0], (const int*)d_in[1], (const int*)d_in[2],
        (const float*)d_in[3], (const float*)d_in[4], (const float*)d_in[5],
        (const float*)d_in[6], (const float*)d_in[7], (const float*)d_in[8],
        (const float*)d_in[9], (const float*)d_in[10], (const float*)d_in[11],
        (const float*)d_in[12], (const float*)d_in[13], (const float*)d_in[14],
        (const float*)d_in[15], (const float*)d_in[16], (const float*)d_in[17],
        (const float*)d_in[18], (float*)d_out);
}